// round 14
// baseline (speedup 1.0000x reference)
#include <cuda_runtime.h>
#include <cuda_fp16.h>
#include <math.h>
#include <stdint.h>

#define NROWS 100000
#define DDIM  512
#define KCOMP 32
#define H1DIM 512
#define H2DIM 256

// ---------------------------------------------------------------------------
// Device scratch
// ---------------------------------------------------------------------------
__device__ __half g_xh [(size_t)NROWS * DDIM];
__device__ __half g_h1h[(size_t)NROWS * H1DIM];
__device__ __half g_h2h[(size_t)NROWS * H2DIM];
__device__ __half g_atth[(size_t)NROWS * KCOMP];
__device__ float  g_S0[KCOMP];
__device__ float  g_S1[KCOMP * DDIM];
__device__ float  g_S2[KCOMP * DDIM];
__device__ float  g_Ck[KCOMP];
__device__ __half g_W1th[(size_t)H1DIM * DDIM];
__device__ __half g_W2th[(size_t)H2DIM * H1DIM];
__device__ __half g_W3th[(size_t)KCOMP * H2DIM];
__device__ __half g_Bm[KCOMP * DDIM];
__device__ __half g_Bv[KCOMP * DDIM];

// fast softplus: max(v,0) + log(1+exp(-|v|))
__device__ __forceinline__ float softplusf(float v) {
    return fmaxf(v, 0.f) + __logf(1.f + __expf(-fabsf(v)));
}
__device__ __forceinline__ uint32_t smem_u32(const void* p) {
    uint32_t a;
    asm("{ .reg .u64 t; cvta.to.shared.u64 t, %1; cvt.u32.u64 %0, t; }"
        : "=r"(a) : "l"(p));
    return a;
}
__device__ __forceinline__ void ldmx4(uint32_t* r, uint32_t addr) {
    asm volatile("ldmatrix.sync.aligned.m8n8.x4.shared.b16 {%0,%1,%2,%3}, [%4];"
        : "=r"(r[0]), "=r"(r[1]), "=r"(r[2]), "=r"(r[3]) : "r"(addr));
}
__device__ __forceinline__ void ldmx4t(uint32_t* r, uint32_t addr) {
    asm volatile("ldmatrix.sync.aligned.m8n8.x4.trans.shared.b16 {%0,%1,%2,%3}, [%4];"
        : "=r"(r[0]), "=r"(r[1]), "=r"(r[2]), "=r"(r[3]) : "r"(addr));
}
__device__ __forceinline__ void mma_f16(float* c, const uint32_t* a, const uint32_t* b) {
    asm volatile("mma.sync.aligned.m16n8k16.row.col.f32.f16.f16.f32 "
        "{%0,%1,%2,%3}, {%4,%5,%6,%7}, {%8,%9}, {%0,%1,%2,%3};"
        : "+f"(c[0]), "+f"(c[1]), "+f"(c[2]), "+f"(c[3])
        : "r"(a[0]), "r"(a[1]), "r"(a[2]), "r"(a[3]), "r"(b[0]), "r"(b[1]));
}
__device__ __forceinline__ uint32_t sqh2(uint32_t v) {
    __half2 h = *(__half2*)&v;
    __half2 o = __hmul2(h, h);
    return *(uint32_t*)&o;
}

// ---------------------------------------------------------------------------
// prep: zero + weight transposes + x->fp16, ONE launch
// ---------------------------------------------------------------------------
#define XTOH_BLOCKS ((NROWS * DDIM) / (256 * 8))   // 25000

__device__ __forceinline__ void tr32(const float* __restrict__ W, __half* __restrict__ Wt,
                                     int K, int Nd, int n0, int k0, float (*t)[33])
{
    int x = threadIdx.x & 31, y = threadIdx.x >> 5;
#pragma unroll
    for (int i = y; i < 32; i += 8)
        t[i][x] = W[(size_t)(k0 + i) * Nd + n0 + x];
    __syncthreads();
#pragma unroll
    for (int i = y; i < 32; i += 8)
        Wt[(size_t)(n0 + i) * K + k0 + x] = __float2half_rn(t[x][i]);
}

__global__ void __launch_bounds__(256)
prep_kernel(const float* __restrict__ W1, const float* __restrict__ W2,
            const float* __restrict__ W3, const float* __restrict__ x)
{
    __shared__ float t[32][33];
    int b = blockIdx.x;
    if (b >= 456) {
        size_t i = ((size_t)(b - 456) * 256 + threadIdx.x) * 8;
        float4 a = *(const float4*)(x + i);
        float4 c = *(const float4*)(x + i + 4);
        __half2 h[4];
        h[0] = __floats2half2_rn(a.x, a.y);
        h[1] = __floats2half2_rn(a.z, a.w);
        h[2] = __floats2half2_rn(c.x, c.y);
        h[3] = __floats2half2_rn(c.z, c.w);
        *(uint4*)(g_xh + i) = *(uint4*)h;
        return;
    }
    if (b < 256) {
        tr32(W1, g_W1th, DDIM, H1DIM, (b & 15) * 32, (b >> 4) * 32, t);
    } else if (b < 384) {
        int bb = b - 256;
        tr32(W2, g_W2th, H1DIM, H2DIM, (bb & 7) * 32, (bb >> 3) * 32, t);
    } else if (b < 392) {
        int bb = b - 384;
        tr32(W3, g_W3th, H2DIM, KCOMP, 0, bb * 32, t);
    } else {
        int i = (b - 392) * 256 + threadIdx.x;
        if (i < KCOMP) g_S0[i] = 0.f;
        if (i < KCOMP * DDIM) { g_S1[i] = 0.f; g_S2[i] = 0.f; }
    }
}

// ---------------------------------------------------------------------------
// fp16 GEMM + bias + softplus (round-8 config + smem bias)
// ---------------------------------------------------------------------------
#define AST  40
#define ASTB 80
#define STGH (128 * AST)
#define STGB (STGH * 2)
#define GEMM_SMEM (4 * STGB)

__global__ void __launch_bounds__(256)
gemm_h(const __half* __restrict__ A, const __half* __restrict__ Bt,
       const float* __restrict__ bias, __half* __restrict__ C,
       int M, int Nd)
{
    extern __shared__ char smraw[];
    __half* Asm = (__half*)smraw;
    __half* Bsm = (__half*)(smraw + 2 * STGB);
    __shared__ float sbias[128];
    const uint32_t sb = smem_u32(smraw);

    const int tid = threadIdx.x, lane = tid & 31, warp = tid >> 5;
    const int wm = warp >> 1, wn = warp & 1;
    const int m0 = blockIdx.y * 128, n0 = blockIdx.x * 128;

    if (tid < 128) sbias[tid] = bias[n0 + tid];

    float acc[2][8][4];
#pragma unroll
    for (int i = 0; i < 2; i++)
#pragma unroll
        for (int j = 0; j < 8; j++)
#pragma unroll
            for (int q = 0; q < 4; q++) acc[i][j][q] = 0.f;

    const int rh[2] = { tid >> 2, (tid + 256) >> 2 };
    const int c8 = (tid & 3) * 8;

#pragma unroll
    for (int q = 0; q < 2; q++) {
        int r = rh[q];
        uint4 va = (m0 + r < M) ? *(const uint4*)(A + (size_t)(m0 + r) * 512 + c8)
                                : make_uint4(0, 0, 0, 0);
        *(uint4*)(Asm + r * AST + c8) = va;
        *(uint4*)(Bsm + r * AST + c8) = *(const uint4*)(Bt + (size_t)(n0 + r) * 512 + c8);
    }
    __syncthreads();

    const uint32_t aoff = sb + (wm * 32 + (lane & 15)) * ASTB + (lane >> 4) * 16;
    const uint32_t boff = sb + 2 * STGB
                        + (wn * 64 + (lane & 7) + ((lane >> 4) << 3)) * ASTB
                        + ((lane >> 3) & 1) * 16;

    for (int c = 0; c < 16; c++) {
        const int s = c & 1;
        uint4 pa[2], pb[2];
        if (c < 15) {
            int k0 = (c + 1) * 32;
#pragma unroll
            for (int q = 0; q < 2; q++) {
                int r = rh[q];
                pa[q] = (m0 + r < M) ? *(const uint4*)(A + (size_t)(m0 + r) * 512 + k0 + c8)
                                     : make_uint4(0, 0, 0, 0);
                pb[q] = *(const uint4*)(Bt + (size_t)(n0 + r) * 512 + k0 + c8);
            }
        }

        const uint32_t ab = aoff + s * STGB;
        const uint32_t bb = boff + s * STGB;
#pragma unroll
        for (int ks = 0; ks < 2; ks++) {
            uint32_t a0[4], a1[4];
            ldmx4(a0, ab + ks * 32);
            ldmx4(a1, ab + ks * 32 + 16 * ASTB);
#pragma unroll
            for (int p = 0; p < 4; p++) {
                uint32_t br[4];
                ldmx4(br, bb + ks * 32 + p * 16 * ASTB);
                mma_f16(acc[0][2 * p],     a0, br);
                mma_f16(acc[0][2 * p + 1], a0, br + 2);
                mma_f16(acc[1][2 * p],     a1, br);
                mma_f16(acc[1][2 * p + 1], a1, br + 2);
            }
        }

        if (c < 15) {
            __half* Ad = Asm + (s ^ 1) * STGH;
            __half* Bd = Bsm + (s ^ 1) * STGH;
#pragma unroll
            for (int q = 0; q < 2; q++) {
                *(uint4*)(Ad + rh[q] * AST + c8) = pa[q];
                *(uint4*)(Bd + rh[q] * AST + c8) = pb[q];
            }
            __syncthreads();
        }
    }

    const int gid = lane >> 2, tig = lane & 3;
#pragma unroll
    for (int i = 0; i < 2; i++) {
        int r = m0 + wm * 32 + i * 16 + gid;
#pragma unroll
        for (int j = 0; j < 8; j++) {
            int cl = wn * 64 + j * 8 + 2 * tig;
            int col = n0 + cl;
            float b0 = sbias[cl], b1 = sbias[cl + 1];
            if (r < M)
                *(__half2*)(C + (size_t)r * Nd + col) =
                    __floats2half2_rn(softplusf(acc[i][j][0] + b0),
                                      softplusf(acc[i][j][1] + b1));
            if (r + 8 < M)
                *(__half2*)(C + (size_t)(r + 8) * Nd + col) =
                    __floats2half2_rn(softplusf(acc[i][j][2] + b0),
                                      softplusf(acc[i][j][3] + b1));
        }
    }
}

// ---------------------------------------------------------------------------
// attn via MMA: 128 thr / 4 warps, 64 rows/block -> 49.5KB smem, 4 CTAs/SM
// ---------------------------------------------------------------------------
#define AT_ST 264
#define AT_STB (AT_ST * 2)
#define AT_H2B (64 * AT_STB)
#define ATT_SMEM (AT_H2B + 32 * AT_STB)

__global__ void __launch_bounds__(128)
attn_mma(const float* __restrict__ b3)
{
    extern __shared__ char smraw[];
    __half* h2s = (__half*)smraw;                 // [64][264]
    __half* w3s = (__half*)(smraw + AT_H2B);      // [32][264]
    __shared__ float ssum[KCOMP];
    __shared__ float b3s[KCOMP];
    const uint32_t sb = smem_u32(smraw);

    const int tid = threadIdx.x, lane = tid & 31, w = tid >> 5;
    const int r0 = blockIdx.x * 64;

    if (tid < KCOMP) { ssum[tid] = 0.f; b3s[tid] = b3[tid]; }

#pragma unroll
    for (int q = 0; q < 8; q++) {
        int u = tid + q * 128;
        *(uint4*)(w3s + (u >> 5) * AT_ST + (u & 31) * 8) =
            *(const uint4*)(g_W3th + (u >> 5) * 256 + (u & 31) * 8);
    }
#pragma unroll
    for (int q = 0; q < 16; q++) {
        int u = tid + q * 128;
        int row = u >> 5, col = (u & 31) * 8;
        uint4 v = (r0 + row < NROWS)
            ? *(const uint4*)(g_h2h + (size_t)(r0 + row) * 256 + col)
            : make_uint4(0, 0, 0, 0);
        *(uint4*)(h2s + row * AT_ST + col) = v;
    }
    __syncthreads();

    float acc[4][4];
#pragma unroll
    for (int j = 0; j < 4; j++)
#pragma unroll
        for (int q = 0; q < 4; q++) acc[j][q] = 0.f;

    const uint32_t aoff = sb + (w * 16 + (lane & 15)) * AT_STB + (lane >> 4) * 16;
    const uint32_t boff0 = sb + AT_H2B
                         + ((lane & 7) + ((lane >> 4) << 3)) * AT_STB
                         + ((lane >> 3) & 1) * 16;
    const uint32_t boff1 = boff0 + 16 * AT_STB;

#pragma unroll
    for (int c = 0; c < 16; c++) {
        uint32_t a[4], b0[4], b1[4];
        ldmx4(a,  aoff  + c * 32);
        ldmx4(b0, boff0 + c * 32);
        ldmx4(b1, boff1 + c * 32);
        mma_f16(acc[0], a, b0);
        mma_f16(acc[1], a, b0 + 2);
        mma_f16(acc[2], a, b1);
        mma_f16(acc[3], a, b1 + 2);
    }

    const int g = lane >> 2, t = lane & 3;
    const int rowA = r0 + w * 16 + g, rowB = rowA + 8;
    float vA[8], vB[8];
#pragma unroll
    for (int j = 0; j < 4; j++) {
        int col = 8 * j + 2 * t;
        vA[2 * j]     = acc[j][0] + b3s[col];
        vA[2 * j + 1] = acc[j][1] + b3s[col + 1];
        vB[2 * j]     = acc[j][2] + b3s[col];
        vB[2 * j + 1] = acc[j][3] + b3s[col + 1];
    }
    float mA = vA[0], mB = vB[0];
#pragma unroll
    for (int i = 1; i < 8; i++) { mA = fmaxf(mA, vA[i]); mB = fmaxf(mB, vB[i]); }
    mA = fmaxf(mA, __shfl_xor_sync(0xffffffffu, mA, 1));
    mA = fmaxf(mA, __shfl_xor_sync(0xffffffffu, mA, 2));
    mB = fmaxf(mB, __shfl_xor_sync(0xffffffffu, mB, 1));
    mB = fmaxf(mB, __shfl_xor_sync(0xffffffffu, mB, 2));
    float sA = 0.f, sB = 0.f;
#pragma unroll
    for (int i = 0; i < 8; i++) {
        vA[i] = __expf(vA[i] - mA); sA += vA[i];
        vB[i] = __expf(vB[i] - mB); sB += vB[i];
    }
    sA += __shfl_xor_sync(0xffffffffu, sA, 1);
    sA += __shfl_xor_sync(0xffffffffu, sA, 2);
    sB += __shfl_xor_sync(0xffffffffu, sB, 1);
    sB += __shfl_xor_sync(0xffffffffu, sB, 2);
    const float rA = 1.f / sA, rB = 1.f / sB;

    float colsum[8];
#pragma unroll
    for (int i = 0; i < 8; i++) colsum[i] = 0.f;

    if (rowA < NROWS) {
#pragma unroll
        for (int j = 0; j < 4; j++) {
            int col = 8 * j + 2 * t;
            float p0 = vA[2 * j] * rA, p1 = vA[2 * j + 1] * rA;
            *(__half2*)(g_atth + (size_t)rowA * KCOMP + col) = __floats2half2_rn(p0, p1);
            colsum[2 * j] += p0; colsum[2 * j + 1] += p1;
        }
    }
    if (rowB < NROWS) {
#pragma unroll
        for (int j = 0; j < 4; j++) {
            int col = 8 * j + 2 * t;
            float p0 = vB[2 * j] * rB, p1 = vB[2 * j + 1] * rB;
            *(__half2*)(g_atth + (size_t)rowB * KCOMP + col) = __floats2half2_rn(p0, p1);
            colsum[2 * j] += p0; colsum[2 * j + 1] += p1;
        }
    }

#pragma unroll
    for (int o = 4; o <= 16; o <<= 1)
#pragma unroll
        for (int i = 0; i < 8; i++)
            colsum[i] += __shfl_xor_sync(0xffffffffu, colsum[i], o);

    if (g == 0) {
#pragma unroll
        for (int j = 0; j < 4; j++) {
            int col = 8 * j + 2 * t;
            atomicAdd(&ssum[col],     colsum[2 * j]);
            atomicAdd(&ssum[col + 1], colsum[2 * j + 1]);
        }
    }
    __syncthreads();
    if (tid < KCOMP) atomicAdd(&g_S0[tid], ssum[tid]);
}

// ---------------------------------------------------------------------------
// stats via MMA: SCH=1408 (round-13 version)
// ---------------------------------------------------------------------------
#define SCH 1408
#define SA_ST 40
#define SX_ST 136

__global__ void __launch_bounds__(256)
stats_mma()
{
    __shared__ __half attS[2][64][SA_ST];
    __shared__ __half xS[2][64][SX_ST];
    const uint32_t sbA = smem_u32(&attS[0][0][0]);
    const uint32_t sbX = smem_u32(&xS[0][0][0]);

    const int tid = threadIdx.x, lane = tid & 31, w = tid >> 5;
    const int n0 = blockIdx.x * SCH;
    const int d0 = blockIdx.y * 128;

    float s1[2][2][4], s2[2][2][4];
#pragma unroll
    for (int i = 0; i < 2; i++)
#pragma unroll
        for (int j = 0; j < 2; j++)
#pragma unroll
            for (int q = 0; q < 4; q++) { s1[i][j][q] = 0.f; s2[i][j][q] = 0.f; }

    {
        int row = tid >> 2, col = (tid & 3) * 8;
        uint4 v = (n0 + row < NROWS)
            ? *(const uint4*)(g_atth + (size_t)(n0 + row) * KCOMP + col)
            : make_uint4(0, 0, 0, 0);
        *(uint4*)(&attS[0][row][col]) = v;
    }
#pragma unroll
    for (int q = 0; q < 4; q++) {
        int u = tid + q * 256, row = u >> 4, col = (u & 15) * 8;
        uint4 v = (n0 + row < NROWS)
            ? *(const uint4*)(g_xh + (size_t)(n0 + row) * DDIM + d0 + col)
            : make_uint4(0, 0, 0, 0);
        *(uint4*)(&xS[0][row][col]) = v;
    }
    __syncthreads();

    const uint32_t aoff = sbA + ((lane & 7) + ((lane >> 4) << 3)) * (SA_ST * 2)
                        + ((lane >> 3) & 1) * 16;
    const uint32_t boff = sbX + (lane & 15) * (SX_ST * 2) + (lane >> 4) * 16 + w * 32;

    for (int step = 0; step < SCH / 64; step++) {
        const int s = step & 1;
        uint4 pa, px[4];
        if (step < SCH / 64 - 1) {
            int nb = n0 + (step + 1) * 64;
            {
                int row = tid >> 2, col = (tid & 3) * 8;
                pa = (nb + row < NROWS)
                    ? *(const uint4*)(g_atth + (size_t)(nb + row) * KCOMP + col)
                    : make_uint4(0, 0, 0, 0);
            }
#pragma unroll
            for (int q = 0; q < 4; q++) {
                int u = tid + q * 256, row = u >> 4, col = (u & 15) * 8;
                px[q] = (nb + row < NROWS)
                    ? *(const uint4*)(g_xh + (size_t)(nb + row) * DDIM + d0 + col)
                    : make_uint4(0, 0, 0, 0);
            }
        }

        const uint32_t as = aoff + s * (64 * SA_ST * 2);
        const uint32_t bs = boff + s * (64 * SX_ST * 2);
#pragma unroll
        for (int t16 = 0; t16 < 4; t16++) {
            uint32_t a0[4], a1[4], b[4], b2[4];
            ldmx4t(a0, as + t16 * (16 * SA_ST * 2));
            ldmx4t(a1, as + t16 * (16 * SA_ST * 2) + 32);
            ldmx4t(b,  bs + t16 * (16 * SX_ST * 2));
#pragma unroll
            for (int i = 0; i < 4; i++) b2[i] = sqh2(b[i]);
            mma_f16(s1[0][0], a0, b);
            mma_f16(s1[0][1], a0, b + 2);
            mma_f16(s1[1][0], a1, b);
            mma_f16(s1[1][1], a1, b + 2);
            mma_f16(s2[0][0], a0, b2);
            mma_f16(s2[0][1], a0, b2 + 2);
            mma_f16(s2[1][0], a1, b2);
            mma_f16(s2[1][1], a1, b2 + 2);
        }

        if (step < SCH / 64 - 1) {
            __syncthreads();
            {
                int row = tid >> 2, col = (tid & 3) * 8;
                *(uint4*)(&attS[s ^ 1][row][col]) = pa;
            }
#pragma unroll
            for (int q = 0; q < 4; q++) {
                int u = tid + q * 256;
                *(uint4*)(&xS[s ^ 1][u >> 4][(u & 15) * 8]) = px[q];
            }
            __syncthreads();
        }
    }

    const int g = lane >> 2, t = lane & 3;
#pragma unroll
    for (int i = 0; i < 2; i++) {
#pragma unroll
        for (int j = 0; j < 2; j++) {
            int kc = i * 16 + g;
            int d  = d0 + w * 16 + j * 8 + 2 * t;
            atomicAdd(&g_S1[kc * DDIM + d],           s1[i][j][0]);
            atomicAdd(&g_S1[kc * DDIM + d + 1],       s1[i][j][1]);
            atomicAdd(&g_S1[(kc + 8) * DDIM + d],     s1[i][j][2]);
            atomicAdd(&g_S1[(kc + 8) * DDIM + d + 1], s1[i][j][3]);
            atomicAdd(&g_S2[kc * DDIM + d],           s2[i][j][0]);
            atomicAdd(&g_S2[kc * DDIM + d + 1],       s2[i][j][1]);
            atomicAdd(&g_S2[(kc + 8) * DDIM + d],     s2[i][j][2]);
            atomicAdd(&g_S2[(kc + 8) * DDIM + d + 1], s2[i][j][3]);
        }
    }
}

// ---------------------------------------------------------------------------
__global__ void __launch_bounds__(256)
finalize_kernel(float* __restrict__ out_vars)
{
    const int k = blockIdx.x;
    const int t = threadIdx.x;
    const float inv_s0 = 1.0f / g_S0[k];

    float csum = 0.f;
    for (int d = t; d < DDIM; d += 256) {
        float mean = g_S1[k * DDIM + d] * inv_s0;
        float ex2  = g_S2[k * DDIM + d] * inv_s0;
        float var  = ex2 - mean * mean;
        float iv   = 1.0f / var;
        float miv  = mean * iv;
        out_vars[k * DDIM + d] = var;
        g_Bm[k * DDIM + d] = __float2half_rn(miv);
        g_Bv[k * DDIM + d] = __float2half_rn(-0.5f * iv);
        csum += mean * miv + logf(var);
    }

    __shared__ float red[256];
    red[t] = csum;
    __syncthreads();
    if (t < 128) red[t] += red[t + 128];
    __syncthreads();
    if (t < 64) red[t] += red[t + 64];
    __syncthreads();
    if (t < 32) {
        float v = red[t] + red[t + 32];
#pragma unroll
        for (int o = 16; o > 0; o >>= 1) v += __shfl_xor_sync(0xffffffffu, v, o);
        if (t == 0)
            g_Ck[k] = -0.5f * v - (float)DDIM * 0.9189385332046727f;
    }
}

// ---------------------------------------------------------------------------
// GMM output (round-11/13 persistent-B version, BM=128, 2 CTAs/SM)
// ---------------------------------------------------------------------------
#define GAST  40
#define GASTB 80
#define GSTGH (128 * GAST)
#define GB_ST 520
#define GB_STB (GB_ST * 2)
#define G_BMOFF 20480
#define G_BVOFF (G_BMOFF + 32 * GB_STB)
#define GMM_SMEM (G_BVOFF + 32 * GB_STB)

__global__ void __launch_bounds__(256)
gmm_mma(float* __restrict__ out)
{
    extern __shared__ char smraw[];
    __half* Ax  = (__half*)smraw;
    __half* Bms = (__half*)(smraw + G_BMOFF);
    __half* Bvs = (__half*)(smraw + G_BVOFF);
    __shared__ float sck[KCOMP];
    const uint32_t sbA = smem_u32(smraw);

    const int tid = threadIdx.x, lane = tid & 31, w = tid >> 5;
    const int m0 = blockIdx.x * 128;

    if (tid < KCOMP) sck[tid] = g_Ck[tid];

    float acc[4][4];
#pragma unroll
    for (int j = 0; j < 4; j++)
#pragma unroll
        for (int q = 0; q < 4; q++) acc[j][q] = 0.f;

#pragma unroll
    for (int q = 0; q < 8; q++) {
        int u = tid + q * 256;
        int row = u >> 6, col = (u & 63) * 8;
        *(uint4*)(Bms + row * GB_ST + col) = *(const uint4*)(g_Bm + row * DDIM + col);
        *(uint4*)(Bvs + row * GB_ST + col) = *(const uint4*)(g_Bv + row * DDIM + col);
    }

    const int arow[2] = { tid >> 2, (tid + 256) >> 2 };
    const int ac8 = (tid & 3) * 8;

#pragma unroll
    for (int q = 0; q < 2; q++) {
        int r = arow[q];
        uint4 v = (m0 + r < NROWS) ? *(const uint4*)(g_xh + (size_t)(m0 + r) * DDIM + ac8)
                                   : make_uint4(0, 0, 0, 0);
        *(uint4*)(Ax + r * GAST + ac8) = v;
    }
    __syncthreads();

    const uint32_t aoff = sbA + (w * 16 + (lane & 15)) * GASTB + (lane >> 4) * 16;
    const uint32_t moff = sbA + G_BMOFF
                        + ((lane & 7) + ((lane >> 4) << 3)) * GB_STB + ((lane >> 3) & 1) * 16;
    const uint32_t voff = sbA + G_BVOFF
                        + ((lane & 7) + ((lane >> 4) << 3)) * GB_STB + ((lane >> 3) & 1) * 16;

    for (int c = 0; c < 16; c++) {
        const int s = c & 1;
        uint4 pa[2];
        if (c < 15) {
            int k0 = (c + 1) * 32;
#pragma unroll
            for (int q = 0; q < 2; q++) {
                int r = arow[q];
                pa[q] = (m0 + r < NROWS) ? *(const uint4*)(g_xh + (size_t)(m0 + r) * DDIM + k0 + ac8)
                                         : make_uint4(0, 0, 0, 0);
            }
        }

        const uint32_t as = aoff + s * (128 * GASTB);
#pragma unroll
        for (int ks = 0; ks < 2; ks++) {
            const uint32_t bcol = c * 64 + ks * 32;
            uint32_t a[4], a2[4];
            ldmx4(a, as + ks * 32);
#pragma unroll
            for (int i = 0; i < 4; i++) a2[i] = sqh2(a[i]);
#pragma unroll
            for (int p = 0; p < 2; p++) {
                uint32_t bm[4], bv[4];
                ldmx4(bm, moff + bcol + p * 16 * GB_STB);
                ldmx4(bv, voff + bcol + p * 16 * GB_STB);
                mma_f16(acc[2 * p],     a,  bm);
                mma_f16(acc[2 * p + 1], a,  bm + 2);
                mma_f16(acc[2 * p],     a2, bv);
                mma_f16(acc[2 * p + 1], a2, bv + 2);
            }
        }

        if (c < 15) {
            __half* Ad = Ax + (s ^ 1) * GSTGH;
#pragma unroll
            for (int q = 0; q < 2; q++)
                *(uint4*)(Ad + arow[q] * GAST + ac8) = pa[q];
            __syncthreads();
        }
    }

    const int g = lane >> 2, t = lane & 3;
    const int r0 = m0 + w * 16 + g;
#pragma unroll
    for (int j = 0; j < 4; j++) {
        int col = j * 8 + 2 * t;
        float ck0 = sck[col], ck1 = sck[col + 1];
        if (r0 < NROWS) {
            float2 o = { acc[j][0] + ck0, acc[j][1] + ck1 };
            *(float2*)(out + (size_t)r0 * KCOMP + col) = o;
        }
        if (r0 + 8 < NROWS) {
            float2 o = { acc[j][2] + ck0, acc[j][3] + ck1 };
            *(float2*)(out + (size_t)(r0 + 8) * KCOMP + col) = o;
        }
    }
}

// ---------------------------------------------------------------------------
// Launch
// ---------------------------------------------------------------------------
extern "C" void kernel_launch(void* const* d_in, const int* in_sizes, int n_in,
                              void* d_out, int out_size)
{
    const float* x  = (const float*)d_in[0];
    const float* W1 = (const float*)d_in[1];
    const float* b1 = (const float*)d_in[2];
    const float* W2 = (const float*)d_in[3];
    const float* b2 = (const float*)d_in[4];
    const float* W3 = (const float*)d_in[5];
    const float* b3 = (const float*)d_in[6];
    float* out = (float*)d_out;

    __half *xhp = nullptr, *h1p = nullptr, *h2p = nullptr;
    __half *w1tp = nullptr, *w2tp = nullptr;
    cudaGetSymbolAddress((void**)&xhp, g_xh);
    cudaGetSymbolAddress((void**)&h1p, g_h1h);
    cudaGetSymbolAddress((void**)&h2p, g_h2h);
    cudaGetSymbolAddress((void**)&w1tp, g_W1th);
    cudaGetSymbolAddress((void**)&w2tp, g_W2th);

    cudaFuncSetAttribute(gemm_h,   cudaFuncAttributeMaxDynamicSharedMemorySize, GEMM_SMEM);
    cudaFuncSetAttribute(attn_mma, cudaFuncAttributeMaxDynamicSharedMemorySize, ATT_SMEM);
    cudaFuncSetAttribute(gmm_mma,  cudaFuncAttributeMaxDynamicSharedMemorySize, GMM_SMEM);

    const int mtiles = (NROWS + 127) / 128;  // 782

    // 0) prep: zero + weight transposes + x->fp16
    prep_kernel<<<456 + XTOH_BLOCKS, 256>>>(W1, W2, W3, x);

    // 1) h1 = softplus(x @ W1 + b1)
    gemm_h<<<dim3(H1DIM / 128, mtiles), 256, GEMM_SMEM>>>(xhp, w1tp, b1, h1p, NROWS, H1DIM);

    // 2) h2 = softplus(h1 @ W2 + b2)
    gemm_h<<<dim3(H2DIM / 128, mtiles), 256, GEMM_SMEM>>>(h1p, w2tp, b2, h2p, NROWS, H2DIM);

    // 3) att = softmax(h2 @ W3 + b3)  [64 rows/block, 4 CTAs/SM]
    attn_mma<<<(NROWS + 63) / 64, 128, ATT_SMEM>>>(b3);

    // 4) weighted stats (288 blocks, balanced wave)
    stats_mma<<<dim3((NROWS + SCH - 1) / SCH, DDIM / 128), 256>>>();

    // 5) finalize: vars output + Bm/Bv/Ck
    finalize_kernel<<<KCOMP, 256>>>(out + (size_t)NROWS * KCOMP);

    // 6) GMM log-likelihood via MMA
    gmm_mma<<<mtiles, 256, GMM_SMEM>>>(out);
}

// round 15
// speedup vs baseline: 1.0208x; 1.0208x over previous
#include <cuda_runtime.h>
#include <cuda_fp16.h>
#include <math.h>
#include <stdint.h>

#define NROWS 100000
#define DDIM  512
#define KCOMP 32
#define H1DIM 512
#define H2DIM 256

// ---------------------------------------------------------------------------
// Device scratch
// ---------------------------------------------------------------------------
__device__ __half g_xh [(size_t)NROWS * DDIM];
__device__ __half g_h1h[(size_t)NROWS * H1DIM];
__device__ __half g_h2h[(size_t)NROWS * H2DIM];
__device__ __half g_atth[(size_t)NROWS * KCOMP];
__device__ float  g_S0[KCOMP];
__device__ float  g_S1[KCOMP * DDIM];
__device__ float  g_S2[KCOMP * DDIM];
__device__ float  g_Ck[KCOMP];
__device__ __half g_W1th[(size_t)H1DIM * DDIM];
__device__ __half g_W2th[(size_t)H2DIM * H1DIM];
__device__ __half g_W3th[(size_t)KCOMP * H2DIM];
__device__ __half g_Bm[KCOMP * DDIM];
__device__ __half g_Bv[KCOMP * DDIM];

// fast softplus: max(v,0) + log(1+exp(-|v|))
__device__ __forceinline__ float softplusf(float v) {
    return fmaxf(v, 0.f) + __logf(1.f + __expf(-fabsf(v)));
}
__device__ __forceinline__ uint32_t smem_u32(const void* p) {
    uint32_t a;
    asm("{ .reg .u64 t; cvta.to.shared.u64 t, %1; cvt.u32.u64 %0, t; }"
        : "=r"(a) : "l"(p));
    return a;
}
__device__ __forceinline__ void ldmx4(uint32_t* r, uint32_t addr) {
    asm volatile("ldmatrix.sync.aligned.m8n8.x4.shared.b16 {%0,%1,%2,%3}, [%4];"
        : "=r"(r[0]), "=r"(r[1]), "=r"(r[2]), "=r"(r[3]) : "r"(addr));
}
__device__ __forceinline__ void ldmx4t(uint32_t* r, uint32_t addr) {
    asm volatile("ldmatrix.sync.aligned.m8n8.x4.trans.shared.b16 {%0,%1,%2,%3}, [%4];"
        : "=r"(r[0]), "=r"(r[1]), "=r"(r[2]), "=r"(r[3]) : "r"(addr));
}
__device__ __forceinline__ void mma_f16(float* c, const uint32_t* a, const uint32_t* b) {
    asm volatile("mma.sync.aligned.m16n8k16.row.col.f32.f16.f16.f32 "
        "{%0,%1,%2,%3}, {%4,%5,%6,%7}, {%8,%9}, {%0,%1,%2,%3};"
        : "+f"(c[0]), "+f"(c[1]), "+f"(c[2]), "+f"(c[3])
        : "r"(a[0]), "r"(a[1]), "r"(a[2]), "r"(a[3]), "r"(b[0]), "r"(b[1]));
}
__device__ __forceinline__ uint32_t sqh2(uint32_t v) {
    __half2 h = *(__half2*)&v;
    __half2 o = __hmul2(h, h);
    return *(uint32_t*)&o;
}

// ---------------------------------------------------------------------------
// prep: zero + weight transposes + x->fp16, ONE launch
// ---------------------------------------------------------------------------
#define XTOH_BLOCKS ((NROWS * DDIM) / (256 * 8))   // 25000

__device__ __forceinline__ void tr32(const float* __restrict__ W, __half* __restrict__ Wt,
                                     int K, int Nd, int n0, int k0, float (*t)[33])
{
    int x = threadIdx.x & 31, y = threadIdx.x >> 5;
#pragma unroll
    for (int i = y; i < 32; i += 8)
        t[i][x] = W[(size_t)(k0 + i) * Nd + n0 + x];
    __syncthreads();
#pragma unroll
    for (int i = y; i < 32; i += 8)
        Wt[(size_t)(n0 + i) * K + k0 + x] = __float2half_rn(t[x][i]);
}

__global__ void __launch_bounds__(256)
prep_kernel(const float* __restrict__ W1, const float* __restrict__ W2,
            const float* __restrict__ W3, const float* __restrict__ x)
{
    __shared__ float t[32][33];
    int b = blockIdx.x;
    if (b >= 456) {
        size_t i = ((size_t)(b - 456) * 256 + threadIdx.x) * 8;
        float4 a = *(const float4*)(x + i);
        float4 c = *(const float4*)(x + i + 4);
        __half2 h[4];
        h[0] = __floats2half2_rn(a.x, a.y);
        h[1] = __floats2half2_rn(a.z, a.w);
        h[2] = __floats2half2_rn(c.x, c.y);
        h[3] = __floats2half2_rn(c.z, c.w);
        *(uint4*)(g_xh + i) = *(uint4*)h;
        return;
    }
    if (b < 256) {
        tr32(W1, g_W1th, DDIM, H1DIM, (b & 15) * 32, (b >> 4) * 32, t);
    } else if (b < 384) {
        int bb = b - 256;
        tr32(W2, g_W2th, H1DIM, H2DIM, (bb & 7) * 32, (bb >> 3) * 32, t);
    } else if (b < 392) {
        int bb = b - 384;
        tr32(W3, g_W3th, H2DIM, KCOMP, 0, bb * 32, t);
    } else {
        int i = (b - 392) * 256 + threadIdx.x;
        if (i < KCOMP) g_S0[i] = 0.f;
        if (i < KCOMP * DDIM) { g_S1[i] = 0.f; g_S2[i] = 0.f; }
    }
}

// ---------------------------------------------------------------------------
// fp16 GEMM + bias + softplus (ROUND-8 proven: BM=BN=128, 256 thr, 4m x 2n)
// ---------------------------------------------------------------------------
#define AST  40
#define ASTB 80
#define STGH (128 * AST)
#define STGB (STGH * 2)
#define GEMM_SMEM (4 * STGB)

__global__ void __launch_bounds__(256)
gemm_h(const __half* __restrict__ A, const __half* __restrict__ Bt,
       const float* __restrict__ bias, __half* __restrict__ C,
       int M, int Nd)
{
    extern __shared__ char smraw[];
    __half* Asm = (__half*)smraw;
    __half* Bsm = (__half*)(smraw + 2 * STGB);
    const uint32_t sb = smem_u32(smraw);

    const int tid = threadIdx.x, lane = tid & 31, warp = tid >> 5;
    const int wm = warp >> 1, wn = warp & 1;
    const int m0 = blockIdx.y * 128, n0 = blockIdx.x * 128;

    float acc[2][8][4];
#pragma unroll
    for (int i = 0; i < 2; i++)
#pragma unroll
        for (int j = 0; j < 8; j++)
#pragma unroll
            for (int q = 0; q < 4; q++) acc[i][j][q] = 0.f;

    const int rh[2] = { tid >> 2, (tid + 256) >> 2 };
    const int c8 = (tid & 3) * 8;

#pragma unroll
    for (int q = 0; q < 2; q++) {
        int r = rh[q];
        uint4 va = (m0 + r < M) ? *(const uint4*)(A + (size_t)(m0 + r) * 512 + c8)
                                : make_uint4(0, 0, 0, 0);
        *(uint4*)(Asm + r * AST + c8) = va;
        *(uint4*)(Bsm + r * AST + c8) = *(const uint4*)(Bt + (size_t)(n0 + r) * 512 + c8);
    }
    __syncthreads();

    const uint32_t aoff = sb + (wm * 32 + (lane & 15)) * ASTB + (lane >> 4) * 16;
    const uint32_t boff = sb + 2 * STGB
                        + (wn * 64 + (lane & 7) + ((lane >> 4) << 3)) * ASTB
                        + ((lane >> 3) & 1) * 16;

    for (int c = 0; c < 16; c++) {
        const int s = c & 1;
        uint4 pa[2], pb[2];
        if (c < 15) {
            int k0 = (c + 1) * 32;
#pragma unroll
            for (int q = 0; q < 2; q++) {
                int r = rh[q];
                pa[q] = (m0 + r < M) ? *(const uint4*)(A + (size_t)(m0 + r) * 512 + k0 + c8)
                                     : make_uint4(0, 0, 0, 0);
                pb[q] = *(const uint4*)(Bt + (size_t)(n0 + r) * 512 + k0 + c8);
            }
        }

        const uint32_t ab = aoff + s * STGB;
        const uint32_t bb = boff + s * STGB;
#pragma unroll
        for (int ks = 0; ks < 2; ks++) {
            uint32_t a0[4], a1[4];
            ldmx4(a0, ab + ks * 32);
            ldmx4(a1, ab + ks * 32 + 16 * ASTB);
#pragma unroll
            for (int p = 0; p < 4; p++) {
                uint32_t br[4];
                ldmx4(br, bb + ks * 32 + p * 16 * ASTB);
                mma_f16(acc[0][2 * p],     a0, br);
                mma_f16(acc[0][2 * p + 1], a0, br + 2);
                mma_f16(acc[1][2 * p],     a1, br);
                mma_f16(acc[1][2 * p + 1], a1, br + 2);
            }
        }

        if (c < 15) {
            __half* Ad = Asm + (s ^ 1) * STGH;
            __half* Bd = Bsm + (s ^ 1) * STGH;
#pragma unroll
            for (int q = 0; q < 2; q++) {
                *(uint4*)(Ad + rh[q] * AST + c8) = pa[q];
                *(uint4*)(Bd + rh[q] * AST + c8) = pb[q];
            }
            __syncthreads();
        }
    }

    const int gid = lane >> 2, tig = lane & 3;
#pragma unroll
    for (int i = 0; i < 2; i++) {
        int r = m0 + wm * 32 + i * 16 + gid;
#pragma unroll
        for (int j = 0; j < 8; j++) {
            int col = n0 + wn * 64 + j * 8 + 2 * tig;
            float b0 = __ldg(bias + col), b1 = __ldg(bias + col + 1);
            if (r < M)
                *(__half2*)(C + (size_t)r * Nd + col) =
                    __floats2half2_rn(softplusf(acc[i][j][0] + b0),
                                      softplusf(acc[i][j][1] + b1));
            if (r + 8 < M)
                *(__half2*)(C + (size_t)(r + 8) * Nd + col) =
                    __floats2half2_rn(softplusf(acc[i][j][2] + b0),
                                      softplusf(acc[i][j][3] + b1));
        }
    }
}

// ---------------------------------------------------------------------------
// attn via MMA (round-13: 256 thr, 128 rows/block, warp-reduced S0 atomics)
// ---------------------------------------------------------------------------
#define AT_ST 264
#define AT_STB (AT_ST * 2)
#define AT_H2B (128 * AT_STB)
#define ATT_SMEM (AT_H2B + 32 * AT_STB)

__global__ void __launch_bounds__(256)
attn_mma(const float* __restrict__ b3)
{
    extern __shared__ char smraw[];
    __half* h2s = (__half*)smraw;
    __half* w3s = (__half*)(smraw + AT_H2B);
    __shared__ float ssum[KCOMP];
    __shared__ float b3s[KCOMP];
    const uint32_t sb = smem_u32(smraw);

    const int tid = threadIdx.x, lane = tid & 31, w = tid >> 5;
    const int r0 = blockIdx.x * 128;

    if (tid < KCOMP) { ssum[tid] = 0.f; b3s[tid] = b3[tid]; }

#pragma unroll
    for (int q = 0; q < 4; q++) {
        int u = tid + q * 256;
        *(uint4*)(w3s + (u >> 5) * AT_ST + (u & 31) * 8) =
            *(const uint4*)(g_W3th + (u >> 5) * 256 + (u & 31) * 8);
    }
#pragma unroll
    for (int q = 0; q < 16; q++) {
        int u = tid + q * 256;
        int row = u >> 5, col = (u & 31) * 8;
        uint4 v = (r0 + row < NROWS)
            ? *(const uint4*)(g_h2h + (size_t)(r0 + row) * 256 + col)
            : make_uint4(0, 0, 0, 0);
        *(uint4*)(h2s + row * AT_ST + col) = v;
    }
    __syncthreads();

    float acc[4][4];
#pragma unroll
    for (int j = 0; j < 4; j++)
#pragma unroll
        for (int q = 0; q < 4; q++) acc[j][q] = 0.f;

    const uint32_t aoff = sb + (w * 16 + (lane & 15)) * AT_STB + (lane >> 4) * 16;
    const uint32_t boff0 = sb + AT_H2B
                         + ((lane & 7) + ((lane >> 4) << 3)) * AT_STB
                         + ((lane >> 3) & 1) * 16;
    const uint32_t boff1 = boff0 + 16 * AT_STB;

#pragma unroll
    for (int c = 0; c < 16; c++) {
        uint32_t a[4], b0[4], b1[4];
        ldmx4(a,  aoff  + c * 32);
        ldmx4(b0, boff0 + c * 32);
        ldmx4(b1, boff1 + c * 32);
        mma_f16(acc[0], a, b0);
        mma_f16(acc[1], a, b0 + 2);
        mma_f16(acc[2], a, b1);
        mma_f16(acc[3], a, b1 + 2);
    }

    const int g = lane >> 2, t = lane & 3;
    const int rowA = r0 + w * 16 + g, rowB = rowA + 8;
    float vA[8], vB[8];
#pragma unroll
    for (int j = 0; j < 4; j++) {
        int col = 8 * j + 2 * t;
        vA[2 * j]     = acc[j][0] + b3s[col];
        vA[2 * j + 1] = acc[j][1] + b3s[col + 1];
        vB[2 * j]     = acc[j][2] + b3s[col];
        vB[2 * j + 1] = acc[j][3] + b3s[col + 1];
    }
    float mA = vA[0], mB = vB[0];
#pragma unroll
    for (int i = 1; i < 8; i++) { mA = fmaxf(mA, vA[i]); mB = fmaxf(mB, vB[i]); }
    mA = fmaxf(mA, __shfl_xor_sync(0xffffffffu, mA, 1));
    mA = fmaxf(mA, __shfl_xor_sync(0xffffffffu, mA, 2));
    mB = fmaxf(mB, __shfl_xor_sync(0xffffffffu, mB, 1));
    mB = fmaxf(mB, __shfl_xor_sync(0xffffffffu, mB, 2));
    float sA = 0.f, sB = 0.f;
#pragma unroll
    for (int i = 0; i < 8; i++) {
        vA[i] = __expf(vA[i] - mA); sA += vA[i];
        vB[i] = __expf(vB[i] - mB); sB += vB[i];
    }
    sA += __shfl_xor_sync(0xffffffffu, sA, 1);
    sA += __shfl_xor_sync(0xffffffffu, sA, 2);
    sB += __shfl_xor_sync(0xffffffffu, sB, 1);
    sB += __shfl_xor_sync(0xffffffffu, sB, 2);
    const float rA = 1.f / sA, rB = 1.f / sB;

    float colsum[8];
#pragma unroll
    for (int i = 0; i < 8; i++) colsum[i] = 0.f;

    if (rowA < NROWS) {
#pragma unroll
        for (int j = 0; j < 4; j++) {
            int col = 8 * j + 2 * t;
            float p0 = vA[2 * j] * rA, p1 = vA[2 * j + 1] * rA;
            *(__half2*)(g_atth + (size_t)rowA * KCOMP + col) = __floats2half2_rn(p0, p1);
            colsum[2 * j] += p0; colsum[2 * j + 1] += p1;
        }
    }
    if (rowB < NROWS) {
#pragma unroll
        for (int j = 0; j < 4; j++) {
            int col = 8 * j + 2 * t;
            float p0 = vB[2 * j] * rB, p1 = vB[2 * j + 1] * rB;
            *(__half2*)(g_atth + (size_t)rowB * KCOMP + col) = __floats2half2_rn(p0, p1);
            colsum[2 * j] += p0; colsum[2 * j + 1] += p1;
        }
    }

#pragma unroll
    for (int o = 4; o <= 16; o <<= 1)
#pragma unroll
        for (int i = 0; i < 8; i++)
            colsum[i] += __shfl_xor_sync(0xffffffffu, colsum[i], o);

    if (g == 0) {
#pragma unroll
        for (int j = 0; j < 4; j++) {
            int col = 8 * j + 2 * t;
            atomicAdd(&ssum[col],     colsum[2 * j]);
            atomicAdd(&ssum[col + 1], colsum[2 * j + 1]);
        }
    }
    __syncthreads();
    if (tid < KCOMP) atomicAdd(&g_S0[tid], ssum[tid]);
}

// ---------------------------------------------------------------------------
// stats via MMA: SCH=1408 (round-13 version)
// ---------------------------------------------------------------------------
#define SCH 1408
#define SA_ST 40
#define SX_ST 136

__global__ void __launch_bounds__(256)
stats_mma()
{
    __shared__ __half attS[2][64][SA_ST];
    __shared__ __half xS[2][64][SX_ST];
    const uint32_t sbA = smem_u32(&attS[0][0][0]);
    const uint32_t sbX = smem_u32(&xS[0][0][0]);

    const int tid = threadIdx.x, lane = tid & 31, w = tid >> 5;
    const int n0 = blockIdx.x * SCH;
    const int d0 = blockIdx.y * 128;

    float s1[2][2][4], s2[2][2][4];
#pragma unroll
    for (int i = 0; i < 2; i++)
#pragma unroll
        for (int j = 0; j < 2; j++)
#pragma unroll
            for (int q = 0; q < 4; q++) { s1[i][j][q] = 0.f; s2[i][j][q] = 0.f; }

    {
        int row = tid >> 2, col = (tid & 3) * 8;
        uint4 v = (n0 + row < NROWS)
            ? *(const uint4*)(g_atth + (size_t)(n0 + row) * KCOMP + col)
            : make_uint4(0, 0, 0, 0);
        *(uint4*)(&attS[0][row][col]) = v;
    }
#pragma unroll
    for (int q = 0; q < 4; q++) {
        int u = tid + q * 256, row = u >> 4, col = (u & 15) * 8;
        uint4 v = (n0 + row < NROWS)
            ? *(const uint4*)(g_xh + (size_t)(n0 + row) * DDIM + d0 + col)
            : make_uint4(0, 0, 0, 0);
        *(uint4*)(&xS[0][row][col]) = v;
    }
    __syncthreads();

    const uint32_t aoff = sbA + ((lane & 7) + ((lane >> 4) << 3)) * (SA_ST * 2)
                        + ((lane >> 3) & 1) * 16;
    const uint32_t boff = sbX + (lane & 15) * (SX_ST * 2) + (lane >> 4) * 16 + w * 32;

    for (int step = 0; step < SCH / 64; step++) {
        const int s = step & 1;
        uint4 pa, px[4];
        if (step < SCH / 64 - 1) {
            int nb = n0 + (step + 1) * 64;
            {
                int row = tid >> 2, col = (tid & 3) * 8;
                pa = (nb + row < NROWS)
                    ? *(const uint4*)(g_atth + (size_t)(nb + row) * KCOMP + col)
                    : make_uint4(0, 0, 0, 0);
            }
#pragma unroll
            for (int q = 0; q < 4; q++) {
                int u = tid + q * 256, row = u >> 4, col = (u & 15) * 8;
                px[q] = (nb + row < NROWS)
                    ? *(const uint4*)(g_xh + (size_t)(nb + row) * DDIM + d0 + col)
                    : make_uint4(0, 0, 0, 0);
            }
        }

        const uint32_t as = aoff + s * (64 * SA_ST * 2);
        const uint32_t bs = boff + s * (64 * SX_ST * 2);
#pragma unroll
        for (int t16 = 0; t16 < 4; t16++) {
            uint32_t a0[4], a1[4], b[4], b2[4];
            ldmx4t(a0, as + t16 * (16 * SA_ST * 2));
            ldmx4t(a1, as + t16 * (16 * SA_ST * 2) + 32);
            ldmx4t(b,  bs + t16 * (16 * SX_ST * 2));
#pragma unroll
            for (int i = 0; i < 4; i++) b2[i] = sqh2(b[i]);
            mma_f16(s1[0][0], a0, b);
            mma_f16(s1[0][1], a0, b + 2);
            mma_f16(s1[1][0], a1, b);
            mma_f16(s1[1][1], a1, b + 2);
            mma_f16(s2[0][0], a0, b2);
            mma_f16(s2[0][1], a0, b2 + 2);
            mma_f16(s2[1][0], a1, b2);
            mma_f16(s2[1][1], a1, b2 + 2);
        }

        if (step < SCH / 64 - 1) {
            __syncthreads();
            {
                int row = tid >> 2, col = (tid & 3) * 8;
                *(uint4*)(&attS[s ^ 1][row][col]) = pa;
            }
#pragma unroll
            for (int q = 0; q < 4; q++) {
                int u = tid + q * 256;
                *(uint4*)(&xS[s ^ 1][u >> 4][(u & 15) * 8]) = px[q];
            }
            __syncthreads();
        }
    }

    const int g = lane >> 2, t = lane & 3;
#pragma unroll
    for (int i = 0; i < 2; i++) {
#pragma unroll
        for (int j = 0; j < 2; j++) {
            int kc = i * 16 + g;
            int d  = d0 + w * 16 + j * 8 + 2 * t;
            atomicAdd(&g_S1[kc * DDIM + d],           s1[i][j][0]);
            atomicAdd(&g_S1[kc * DDIM + d + 1],       s1[i][j][1]);
            atomicAdd(&g_S1[(kc + 8) * DDIM + d],     s1[i][j][2]);
            atomicAdd(&g_S1[(kc + 8) * DDIM + d + 1], s1[i][j][3]);
            atomicAdd(&g_S2[kc * DDIM + d],           s2[i][j][0]);
            atomicAdd(&g_S2[kc * DDIM + d + 1],       s2[i][j][1]);
            atomicAdd(&g_S2[(kc + 8) * DDIM + d],     s2[i][j][2]);
            atomicAdd(&g_S2[(kc + 8) * DDIM + d + 1], s2[i][j][3]);
        }
    }
}

// ---------------------------------------------------------------------------
__global__ void __launch_bounds__(256)
finalize_kernel(float* __restrict__ out_vars)
{
    const int k = blockIdx.x;
    const int t = threadIdx.x;
    const float inv_s0 = 1.0f / g_S0[k];

    float csum = 0.f;
    for (int d = t; d < DDIM; d += 256) {
        float mean = g_S1[k * DDIM + d] * inv_s0;
        float ex2  = g_S2[k * DDIM + d] * inv_s0;
        float var  = ex2 - mean * mean;
        float iv   = 1.0f / var;
        float miv  = mean * iv;
        out_vars[k * DDIM + d] = var;
        g_Bm[k * DDIM + d] = __float2half_rn(miv);
        g_Bv[k * DDIM + d] = __float2half_rn(-0.5f * iv);
        csum += mean * miv + logf(var);
    }

    __shared__ float red[256];
    red[t] = csum;
    __syncthreads();
    if (t < 128) red[t] += red[t + 128];
    __syncthreads();
    if (t < 64) red[t] += red[t + 64];
    __syncthreads();
    if (t < 32) {
        float v = red[t] + red[t + 32];
#pragma unroll
        for (int o = 16; o > 0; o >>= 1) v += __shfl_xor_sync(0xffffffffu, v, o);
        if (t == 0)
            g_Ck[k] = -0.5f * v - (float)DDIM * 0.9189385332046727f;
    }
}

// ---------------------------------------------------------------------------
// GMM output: persistent B, BM=128, warps 4m x 2n (32 rows x 16 cols each)
// per (c,ks) per warp: 2 A-ldmx4 + 2 B-ldmx4 -> 8 MMAs (ratio 2.0 vs 1.6)
// ---------------------------------------------------------------------------
#define GAST  40
#define GASTB 80
#define GSTGH (128 * GAST)
#define GB_ST 520
#define GB_STB (GB_ST * 2)
#define G_BMOFF 20480
#define G_BVOFF (G_BMOFF + 32 * GB_STB)
#define GMM_SMEM (G_BVOFF + 32 * GB_STB)

__global__ void __launch_bounds__(256)
gmm_mma(float* __restrict__ out)
{
    extern __shared__ char smraw[];
    __half* Ax  = (__half*)smraw;
    __half* Bms = (__half*)(smraw + G_BMOFF);
    __half* Bvs = (__half*)(smraw + G_BVOFF);
    __shared__ float sck[KCOMP];
    const uint32_t sbA = smem_u32(smraw);

    const int tid = threadIdx.x, lane = tid & 31, w = tid >> 5;
    const int wm = w >> 1, wn = w & 1;     // 4 m-warps x 2 n-warps
    const int m0 = blockIdx.x * 128;

    if (tid < KCOMP) sck[tid] = g_Ck[tid];

    float acc[2][2][4];
#pragma unroll
    for (int i = 0; i < 2; i++)
#pragma unroll
        for (int j = 0; j < 2; j++)
#pragma unroll
            for (int q = 0; q < 4; q++) acc[i][j][q] = 0.f;

#pragma unroll
    for (int q = 0; q < 8; q++) {
        int u = tid + q * 256;
        int row = u >> 6, col = (u & 63) * 8;
        *(uint4*)(Bms + row * GB_ST + col) = *(const uint4*)(g_Bm + row * DDIM + col);
        *(uint4*)(Bvs + row * GB_ST + col) = *(const uint4*)(g_Bv + row * DDIM + col);
    }

    const int arow[2] = { tid >> 2, (tid + 256) >> 2 };
    const int ac8 = (tid & 3) * 8;

#pragma unroll
    for (int q = 0; q < 2; q++) {
        int r = arow[q];
        uint4 v = (m0 + r < NROWS) ? *(const uint4*)(g_xh + (size_t)(m0 + r) * DDIM + ac8)
                                   : make_uint4(0, 0, 0, 0);
        *(uint4*)(Ax + r * GAST + ac8) = v;
    }
    __syncthreads();

    const uint32_t aoff = sbA + (wm * 32 + (lane & 15)) * GASTB + (lane >> 4) * 16;
    const uint32_t moff = sbA + G_BMOFF
                        + (wn * 16 + (lane & 7) + ((lane >> 4) << 3)) * GB_STB
                        + ((lane >> 3) & 1) * 16;
    const uint32_t voff = sbA + G_BVOFF
                        + (wn * 16 + (lane & 7) + ((lane >> 4) << 3)) * GB_STB
                        + ((lane >> 3) & 1) * 16;

    for (int c = 0; c < 16; c++) {
        const int s = c & 1;
        uint4 pa[2];
        if (c < 15) {
            int k0 = (c + 1) * 32;
#pragma unroll
            for (int q = 0; q < 2; q++) {
                int r = arow[q];
                pa[q] = (m0 + r < NROWS) ? *(const uint4*)(g_xh + (size_t)(m0 + r) * DDIM + k0 + ac8)
                                         : make_uint4(0, 0, 0, 0);
            }
        }

        const uint32_t as = aoff + s * (128 * GASTB);
#pragma unroll
        for (int ks = 0; ks < 2; ks++) {
            const uint32_t bcol = c * 64 + ks * 32;
            uint32_t a0[4], a1[4], a0s[4], a1s[4];
            ldmx4(a0, as + ks * 32);
            ldmx4(a1, as + ks * 32 + 16 * GASTB);
#pragma unroll
            for (int i = 0; i < 4; i++) { a0s[i] = sqh2(a0[i]); a1s[i] = sqh2(a1[i]); }
            uint32_t bm[4], bv[4];
            ldmx4(bm, moff + bcol);
            ldmx4(bv, voff + bcol);
            mma_f16(acc[0][0], a0,  bm);
            mma_f16(acc[0][1], a0,  bm + 2);
            mma_f16(acc[1][0], a1,  bm);
            mma_f16(acc[1][1], a1,  bm + 2);
            mma_f16(acc[0][0], a0s, bv);
            mma_f16(acc[0][1], a0s, bv + 2);
            mma_f16(acc[1][0], a1s, bv);
            mma_f16(acc[1][1], a1s, bv + 2);
        }

        if (c < 15) {
            __half* Ad = Ax + (s ^ 1) * GSTGH;
#pragma unroll
            for (int q = 0; q < 2; q++)
                *(uint4*)(Ad + arow[q] * GAST + ac8) = pa[q];
            __syncthreads();
        }
    }

    const int g = lane >> 2, t = lane & 3;
#pragma unroll
    for (int i = 0; i < 2; i++) {
        int r0 = m0 + wm * 32 + i * 16 + g;
#pragma unroll
        for (int j = 0; j < 2; j++) {
            int col = wn * 16 + j * 8 + 2 * t;
            float ck0 = sck[col], ck1 = sck[col + 1];
            if (r0 < NROWS) {
                float2 o = { acc[i][j][0] + ck0, acc[i][j][1] + ck1 };
                *(float2*)(out + (size_t)r0 * KCOMP + col) = o;
            }
            if (r0 + 8 < NROWS) {
                float2 o = { acc[i][j][2] + ck0, acc[i][j][3] + ck1 };
                *(float2*)(out + (size_t)(r0 + 8) * KCOMP + col) = o;
            }
        }
    }
}

// ---------------------------------------------------------------------------
// Launch
// ---------------------------------------------------------------------------
extern "C" void kernel_launch(void* const* d_in, const int* in_sizes, int n_in,
                              void* d_out, int out_size)
{
    const float* x  = (const float*)d_in[0];
    const float* W1 = (const float*)d_in[1];
    const float* b1 = (const float*)d_in[2];
    const float* W2 = (const float*)d_in[3];
    const float* b2 = (const float*)d_in[4];
    const float* W3 = (const float*)d_in[5];
    const float* b3 = (const float*)d_in[6];
    float* out = (float*)d_out;

    __half *xhp = nullptr, *h1p = nullptr, *h2p = nullptr;
    __half *w1tp = nullptr, *w2tp = nullptr;
    cudaGetSymbolAddress((void**)&xhp, g_xh);
    cudaGetSymbolAddress((void**)&h1p, g_h1h);
    cudaGetSymbolAddress((void**)&h2p, g_h2h);
    cudaGetSymbolAddress((void**)&w1tp, g_W1th);
    cudaGetSymbolAddress((void**)&w2tp, g_W2th);

    cudaFuncSetAttribute(gemm_h,   cudaFuncAttributeMaxDynamicSharedMemorySize, GEMM_SMEM);
    cudaFuncSetAttribute(attn_mma, cudaFuncAttributeMaxDynamicSharedMemorySize, ATT_SMEM);
    cudaFuncSetAttribute(gmm_mma,  cudaFuncAttributeMaxDynamicSharedMemorySize, GMM_SMEM);

    const int mtiles = (NROWS + 127) / 128;  // 782

    // 0) prep: zero + weight transposes + x->fp16
    prep_kernel<<<456 + XTOH_BLOCKS, 256>>>(W1, W2, W3, x);

    // 1) h1 = softplus(x @ W1 + b1)
    gemm_h<<<dim3(H1DIM / 128, mtiles), 256, GEMM_SMEM>>>(xhp, w1tp, b1, h1p, NROWS, H1DIM);

    // 2) h2 = softplus(h1 @ W2 + b2)
    gemm_h<<<dim3(H2DIM / 128, mtiles), 256, GEMM_SMEM>>>(h1p, w2tp, b2, h2p, NROWS, H2DIM);

    // 3) att = softmax(h2 @ W3 + b3)
    attn_mma<<<(NROWS + 127) / 128, 256, ATT_SMEM>>>(b3);

    // 4) weighted stats (288 blocks, balanced wave)
    stats_mma<<<dim3((NROWS + SCH - 1) / SCH, DDIM / 128), 256>>>();

    // 5) finalize: vars output + Bm/Bv/Ck
    finalize_kernel<<<KCOMP, 256>>>(out + (size_t)NROWS * KCOMP);

    // 6) GMM log-likelihood (4m x 2n warp split)
    gmm_mma<<<mtiles, 256, GMM_SMEM>>>(out);
}